// round 1
// baseline (speedup 1.0000x reference)
#include <cuda_runtime.h>
#include <cuda_bf16.h>
#include <math.h>

// Problem constants
#define MAXE 500000
#define CC 128          // C
#define HH 256          // H
#define ED 72           // EDGE_DIM = 8 * 9
#define EDP 80          // padded K for GEMM1
#define CUTOFF_F 6.0f
#define EPS_F 1e-9f

// -------- device scratch (static, no allocation) --------
__device__ int g_nact;
__device__ int g_ninact;
__device__ int g_active[MAXE];
__device__ int g_inactive[MAXE];
__device__ float g_const_row[CC];

// -------- f32x2 packed helpers --------
__device__ __forceinline__ unsigned long long pk2(float lo, float hi) {
    unsigned long long u;
    asm("mov.b64 %0, {%1, %2};" : "=l"(u) : "f"(lo), "f"(hi));
    return u;
}
__device__ __forceinline__ float2 upk2(unsigned long long u) {
    float lo, hi;
    asm("mov.b64 {%0, %1}, %2;" : "=f"(lo), "=f"(hi) : "l"(u));
    return make_float2(lo, hi);
}
__device__ __forceinline__ void ffma2(unsigned long long &d, unsigned long long a, unsigned long long b) {
    asm("fma.rn.f32x2 %0, %1, %2, %0;" : "+l"(d) : "l"(a), "l"(b));
}

__device__ __forceinline__ float silu_f(float x) {
    return x / (1.0f + expf(-x));
}

__device__ __forceinline__ void warp_reduce2(float &s, float &q) {
#pragma unroll
    for (int o = 16; o > 0; o >>= 1) {
        s += __shfl_xor_sync(0xffffffffu, s, o);
        q += __shfl_xor_sync(0xffffffffu, q, o);
    }
}

// -------- kernel 0: reset counters --------
__global__ void reset_kernel() {
    g_nact = 0;
    g_ninact = 0;
}

// -------- kernel 1: constant output row for zero-feature edges --------
__global__ __launch_bounds__(256) void const_row_kernel(
    const float* __restrict__ b1, const float* __restrict__ W2, const float* __restrict__ b2,
    const float* __restrict__ W3, const float* __restrict__ b3,
    const float* __restrict__ eln_w, const float* __restrict__ eln_b)
{
    __shared__ float s1[HH];
    __shared__ float s2[HH];
    __shared__ float stats[2];
    int t = threadIdx.x;

    s1[t] = silu_f(b1[t]);
    __syncthreads();

    float acc = b2[t];
    for (int k = 0; k < HH; k++) acc += s1[k] * W2[k * HH + t];
    s2[t] = silu_f(acc);
    __syncthreads();

    float val = 0.0f;
    if (t < CC) {
        acc = b3[t];
        for (int k = 0; k < HH; k++) acc += s2[k] * W3[k * CC + t];
        val = acc;
        s1[t] = val;
    }
    __syncthreads();
    if (t == 0) {
        float s = 0.f, sq = 0.f;
        for (int k = 0; k < CC; k++) { s += s1[k]; sq += s1[k] * s1[k]; }
        float mu = s * (1.0f / CC);
        float var = sq * (1.0f / CC) - mu * mu;
        stats[0] = mu;
        stats[1] = rsqrtf(var + 1e-5f);
    }
    __syncthreads();
    if (t < CC) g_const_row[t] = (val - stats[0]) * stats[1] * eln_w[t] + eln_b[t];
}

// -------- kernel 2: node embedding layernorm (warp per row) --------
__global__ __launch_bounds__(256) void node_kernel(
    const int* __restrict__ Z, const float* __restrict__ zt,
    const float* __restrict__ w, const float* __restrict__ b,
    float* __restrict__ out, int N)
{
    int row = blockIdx.x * 8 + (threadIdx.x >> 5);
    int lane = threadIdx.x & 31;
    if (row >= N) return;
    int zi = Z[row];
    float4 v = *(const float4*)(zt + (size_t)zi * CC + lane * 4);
    float s = v.x + v.y + v.z + v.w;
    float q = v.x * v.x + v.y * v.y + v.z * v.z + v.w * v.w;
    warp_reduce2(s, q);
    float mu = s * (1.0f / CC);
    float var = q * (1.0f / CC) - mu * mu;
    float rs = rsqrtf(var + 1e-5f);
    float4 wv = *(const float4*)(w + lane * 4);
    float4 bv = *(const float4*)(b + lane * 4);
    float4 o;
    o.x = (v.x - mu) * rs * wv.x + bv.x;
    o.y = (v.y - mu) * rs * wv.y + bv.y;
    o.z = (v.z - mu) * rs * wv.z + bv.z;
    o.w = (v.w - mu) * rs * wv.w + bv.w;
    *(float4*)(out + (size_t)row * CC + lane * 4) = o;
}

// -------- kernel 3: classify edges into active / inactive lists --------
__global__ __launch_bounds__(256) void prep_kernel(
    const float* __restrict__ pos, const int* __restrict__ snd,
    const int* __restrict__ rcv, int E)
{
    int i = blockIdx.x * blockDim.x + threadIdx.x;
    if (i >= E) return;
    int s = snd[i], r = rcv[i];
    float dx = pos[3 * r + 0] - pos[3 * s + 0];
    float dy = pos[3 * r + 1] - pos[3 * s + 1];
    float dz = pos[3 * r + 2] - pos[3 * s + 2];
    float d = sqrtf(dx * dx + dy * dy + dz * dz);
    if (d < CUTOFF_F) {
        int k = atomicAdd(&g_nact, 1);
        g_active[k] = i;
    } else {
        int k = atomicAdd(&g_ninact, 1);
        g_inactive[k] = i;
    }
}

// -------- kernel 4: fill inactive edge rows with const row (warp per edge) --------
__global__ __launch_bounds__(256) void fill_kernel(float* __restrict__ out_edge)
{
    int gw = (blockIdx.x * blockDim.x + threadIdx.x) >> 5;
    int lane = threadIdx.x & 31;
    if (gw >= g_ninact) return;
    int e = g_inactive[gw];
    float4 v = *(const float4*)(g_const_row + lane * 4);
    *(float4*)(out_edge + (size_t)e * CC + lane * 4) = v;
}

// -------- fused tile GEMM on f32x2 --------
// A: smem column-major [KPAD][64]; W: global row-major [K][NOUT]; Bs: smem [16][128]
// Out: col-major stride 64 (OUT_RM=false) or row-major stride 132 (OUT_RM=true)
template<int K, int KPAD, int NOUT, bool SILU, bool OUT_RM>
__device__ __forceinline__ void tile_gemm(
    const float* __restrict__ A, const float* __restrict__ W,
    const float* __restrict__ bias, float* __restrict__ Bs,
    float* __restrict__ Out, int ty, int tx, int tid)
{
#pragma unroll
    for (int cb = 0; cb < NOUT; cb += 128) {
        unsigned long long acc[4][4];
#pragma unroll
        for (int i = 0; i < 4; i++)
#pragma unroll
            for (int p = 0; p < 4; p++) acc[i][p] = 0ULL;

        for (int k0 = 0; k0 < KPAD; k0 += 16) {
            __syncthreads();
#pragma unroll
            for (int t = 0; t < 8; t++) {
                int idx = tid + t * 256;
                int kk = idx >> 7, cc = idx & 127;
                int kg = k0 + kk;
                Bs[idx] = (kg < K) ? W[kg * NOUT + cb + cc] : 0.0f;
            }
            __syncthreads();
#pragma unroll
            for (int kk = 0; kk < 16; kk++) {
                float4 a  = *(const float4*)(A + (k0 + kk) * 64 + 4 * ty);
                float4 b0 = *(const float4*)(Bs + kk * 128 + 8 * tx);
                float4 b1 = *(const float4*)(Bs + kk * 128 + 8 * tx + 4);
                unsigned long long B0 = pk2(b0.x, b0.y), B1 = pk2(b0.z, b0.w);
                unsigned long long B2 = pk2(b1.x, b1.y), B3 = pk2(b1.z, b1.w);
                float av[4] = {a.x, a.y, a.z, a.w};
#pragma unroll
                for (int i = 0; i < 4; i++) {
                    unsigned long long A2 = pk2(av[i], av[i]);
                    ffma2(acc[i][0], A2, B0);
                    ffma2(acc[i][1], A2, B1);
                    ffma2(acc[i][2], A2, B2);
                    ffma2(acc[i][3], A2, B3);
                }
            }
        }
        // epilogue
#pragma unroll
        for (int p = 0; p < 4; p++) {
            int c0 = cb + 8 * tx + 2 * p;
            float bx = bias[c0], by = bias[c0 + 1];
#pragma unroll
            for (int i = 0; i < 4; i++) {
                float2 v = upk2(acc[i][p]);
                v.x += bx; v.y += by;
                if (SILU) { v.x = silu_f(v.x); v.y = silu_f(v.y); }
                int r = 4 * ty + i;
                if (OUT_RM) {
                    Out[r * 132 + c0]     = v.x;
                    Out[r * 132 + c0 + 1] = v.y;
                } else {
                    Out[c0 * 64 + r]       = v.x;
                    Out[(c0 + 1) * 64 + r] = v.y;
                }
            }
        }
    }
}

// smem layout (floats): sFeat 80*64=5120 | sHa 256*64=16384 | sHb 16384 | Bs 2048 | eidx 64 ints
#define SMEM_BYTES ((5120 + 16384 + 16384 + 2048) * 4 + 64 * 4)

// -------- kernel 5: fused edge MLP over active edges (64 edges per block) --------
__global__ __launch_bounds__(256) void mlp_kernel(
    const float* __restrict__ pos, const int* __restrict__ snd, const int* __restrict__ rcv,
    const float* __restrict__ W1, const float* __restrict__ b1,
    const float* __restrict__ W2, const float* __restrict__ b2,
    const float* __restrict__ W3, const float* __restrict__ b3,
    const float* __restrict__ eln_w, const float* __restrict__ eln_b,
    float* __restrict__ out_edge)
{
    extern __shared__ float smem[];
    float* sFeat = smem;                 // [80][64] col-major
    float* sHa   = smem + 5120;          // [256][64] col-major
    float* sHb   = sHa + 16384;          // [256][64] col-major
    float* Bs    = sHb + 16384;          // [16][128]
    int*   eidx  = (int*)(Bs + 2048);    // [64]
    float* sH3   = sHa;                  // alias: [64][132] row-major (8448 floats)

    int tid = threadIdx.x;
    int base = blockIdx.x * 64;
    int nact = g_nact;
    if (base >= nact) return;
    int count = min(64, nact - base);

    if (tid < 64) eidx[tid] = (tid < count) ? g_active[base + tid] : 0;
    __syncthreads();

    // ---- features: e = tid/4, part = tid%4 handles rbf {2p, 2p+1} x 9 sh ----
    {
        // zero pad rows 72..79 of sFeat
#pragma unroll
        for (int t = 0; t < 2; t++) sFeat[ED * 64 + tid + t * 256] = 0.0f;

        int e = tid >> 2;
        int part = tid & 3;
        if (e < count) {
            int ei = eidx[e];
            int s = snd[ei], r = rcv[ei];
            float vx = pos[3 * r + 0] - pos[3 * s + 0];
            float vy = pos[3 * r + 1] - pos[3 * s + 1];
            float vz = pos[3 * r + 2] - pos[3 * s + 2];
            float d = sqrtf(vx * vx + vy * vy + vz * vz);
            float inv = 1.0f / (d + EPS_F);
            float x = vx * inv, y = vy * inv, z = vz * inv;
            const float s3 = 1.7320508075688772f;
            const float s5 = 2.2360679774997896f;
            const float s15 = 3.8729833462074170f;
            float sh[9];
            sh[0] = 1.0f;
            sh[1] = s3 * x;
            sh[2] = s3 * y;
            sh[3] = s3 * z;
            sh[4] = s15 * x * y;
            sh[5] = s15 * y * z;
            sh[6] = 0.5f * s5 * (3.0f * z * z - 1.0f);
            sh[7] = s15 * x * z;
            sh[8] = 0.5f * s15 * (x * x - y * y);
            float xd = d * (1.0f / CUTOFF_F);
            float xp = xd * xd; xp = xp * xp;                // x^4
            float env = 1.0f - 15.0f * xp + 24.0f * xp * xd - 10.0f * xp * xd * xd;
            const float pref = 0.5773502691896258f;          // sqrt(2/6)
            const float PI_F = 3.14159265358979323846f;
#pragma unroll
            for (int q = 0; q < 2; q++) {
                int nb = part * 2 + q;                       // rbf index 0..7
                float n = (float)(nb + 1);
                float rb = pref * sinf(n * PI_F * d * (1.0f / CUTOFF_F)) * inv;
                float re = rb * env;
#pragma unroll
                for (int m = 0; m < 9; m++)
                    sFeat[(nb * 9 + m) * 64 + e] = re * sh[m];
            }
        }
    }
    __syncthreads();

    int ty = tid >> 4;   // 0..15 -> rows 4ty..4ty+3
    int tx = tid & 15;   // 0..15 -> cols 8tx..8tx+7

    tile_gemm<ED, EDP, HH, true,  false>(sFeat, W1, b1, Bs, sHa, ty, tx, tid);
    tile_gemm<HH, HH,  HH, true,  false>(sHa,   W2, b2, Bs, sHb, ty, tx, tid);
    tile_gemm<HH, HH,  CC, false, true >(sHb,   W3, b3, Bs, sH3, ty, tx, tid);
    __syncthreads();

    // ---- layernorm + scatter write (8 warps x 8 rows) ----
    int w = tid >> 5, lane = tid & 31;
#pragma unroll
    for (int rr = 0; rr < 8; rr++) {
        int r = w * 8 + rr;
        if (r >= count) continue;
        float4 v = *(const float4*)(sH3 + r * 132 + lane * 4);
        float s = v.x + v.y + v.z + v.w;
        float q = v.x * v.x + v.y * v.y + v.z * v.z + v.w * v.w;
        warp_reduce2(s, q);
        float mu = s * (1.0f / CC);
        float var = q * (1.0f / CC) - mu * mu;
        float rs = rsqrtf(var + 1e-5f);
        float4 wv = *(const float4*)(eln_w + lane * 4);
        float4 bv = *(const float4*)(eln_b + lane * 4);
        float4 o;
        o.x = (v.x - mu) * rs * wv.x + bv.x;
        o.y = (v.y - mu) * rs * wv.y + bv.y;
        o.z = (v.z - mu) * rs * wv.z + bv.z;
        o.w = (v.w - mu) * rs * wv.w + bv.w;
        int e = eidx[r];
        *(float4*)(out_edge + (size_t)e * CC + lane * 4) = o;
    }
}

// -------- launch --------
extern "C" void kernel_launch(void* const* d_in, const int* in_sizes, int n_in,
                              void* d_out, int out_size)
{
    const int*   Z     = (const int*)  d_in[0];
    const float* pos   = (const float*)d_in[1];
    const int*   snd   = (const int*)  d_in[2];
    const int*   rcv   = (const int*)  d_in[3];
    const float* zt    = (const float*)d_in[4];
    const float* zln_w = (const float*)d_in[5];
    const float* zln_b = (const float*)d_in[6];
    const float* W1    = (const float*)d_in[7];
    const float* b1    = (const float*)d_in[8];
    const float* W2    = (const float*)d_in[9];
    const float* b2    = (const float*)d_in[10];
    const float* W3    = (const float*)d_in[11];
    const float* b3    = (const float*)d_in[12];
    const float* eln_w = (const float*)d_in[13];
    const float* eln_b = (const float*)d_in[14];

    int N = in_sizes[0];
    int E = in_sizes[2];

    float* out_node = (float*)d_out;
    float* out_edge = out_node + (size_t)N * CC;

    cudaFuncSetAttribute(mlp_kernel, cudaFuncAttributeMaxDynamicSharedMemorySize, SMEM_BYTES);

    reset_kernel<<<1, 1>>>();
    const_row_kernel<<<1, 256>>>(b1, W2, b2, W3, b3, eln_w, eln_b);
    node_kernel<<<(N + 7) / 8, 256>>>(Z, zt, zln_w, zln_b, out_node, N);
    prep_kernel<<<(E + 255) / 256, 256>>>(pos, snd, rcv, E);
    fill_kernel<<<(E + 7) / 8, 256>>>(out_edge);
    mlp_kernel<<<(E + 63) / 64, 256, SMEM_BYTES>>>(pos, snd, rcv,
                                                   W1, b1, W2, b2, W3, b3,
                                                   eln_w, eln_b, out_edge);
}